// round 1
// baseline (speedup 1.0000x reference)
#include <cuda_runtime.h>
#include <cuda_fp16.h>
#include <math.h>

#define S_LEN 8192
#define TAGS 2048
#define NB 148
#define RPB 14            // ceil(2048/148) rows per block
#define TPB 256
#define NWARP 8
#define ALPHA 16.0f
#define START_IDX 0
#define END_IDX 1

// E in smem: RPB rows * 1024 half2 = 57344 B, then reduce scratch
#define E_H2 (RPB * (TAGS / 2))
#define SMEM_BYTES (E_H2 * 4 + 1024 + 2048)

// Persistent state (device globals: no allocation allowed).
__device__ float g_Mbuf[S_LEN + 2];      // Mbuf[t] = max of r_t (Mbuf[0] = 1)
__device__ float g_wbuf[2][TAGS];        // double-buffered carried vector (raw fp32)
__device__ unsigned g_arrive;
__device__ volatile unsigned g_release;

__global__ void crf_init() {
    int i = blockIdx.x * blockDim.x + threadIdx.x;
    int n = gridDim.x * blockDim.x;
    for (int t = i; t < S_LEN + 2; t += n) g_Mbuf[t] = (t == 0) ? 1.0f : 0.0f;
    for (int j = i; j < TAGS; j += n) {
        g_wbuf[0][j] = (j == START_IDX) ? 1.0f : 0.0f;
        g_wbuf[1][j] = 0.0f;
    }
    if (i == 0) { g_arrive = 0u; g_release = 0u; }
}

__global__ void __launch_bounds__(TPB, 1) crf_main(const float* __restrict__ h,
                                                   const float* __restrict__ tr,
                                                   float* __restrict__ out) {
    extern __shared__ __half2 smem[];
    __half2* E = smem;
    float* partial = (float*)(smem + E_H2);       // [RPB][NWARP] (448 B, inside 1024 B pad)
    __shared__ int s_max;

    const int tid = threadIdx.x;
    const int warp = tid >> 5, lane = tid & 31;
    const int b = blockIdx.x;
    const int row0 = b * RPB;
    int nrows = TAGS - row0;
    if (nrows > RPB) nrows = RPB;
    if (nrows < 0) nrows = 0;

    // One-time: E = exp(transitions) rows for this block -> smem (fp16), pad rows zeroed.
    for (int idx = tid; idx < E_H2; idx += TPB) {
        int r = idx / (TAGS / 2);
        int j2 = idx % (TAGS / 2);
        __half2 val;
        if (r < nrows) {
            float2 t2 = ((const float2*)(tr + (size_t)(row0 + r) * TAGS))[j2];
            val = __floats2half2_rn(__expf(t2.x), __expf(t2.y));
        } else {
            val = __floats2half2_rn(0.f, 0.f);
        }
        E[idx] = val;
    }
    if (tid == 0) s_max = 0;
    __syncthreads();

    const int j0 = (warp << 8) + (lane << 3);   // this lane's 8-float chunk of v
    const int e0 = j0 >> 1;                     // half2 index within a row

    for (int t = 0; t < S_LEN; t++) {
        const float* rin = g_wbuf[t & 1];
        float* rout = g_wbuf[(t + 1) & 1];

        // v = (alpha / m_t) * r_t  -> half2 in registers (L2 reads, bypass L1)
        float m = __ldcg(&g_Mbuf[t]);
        float s = ALPHA / m;
        float4 x = __ldcg((const float4*)(rin + j0));
        float4 y = __ldcg((const float4*)(rin + j0) + 1);
        __half2 v0 = __floats2half2_rn(x.x * s, x.y * s);
        __half2 v1 = __floats2half2_rn(x.z * s, x.w * s);
        __half2 v2 = __floats2half2_rn(y.x * s, y.y * s);
        __half2 v3 = __floats2half2_rn(y.z * s, y.w * s);

        // Partial dot products: each warp covers a 256-wide j-chunk of all rows.
#pragma unroll
        for (int r = 0; r < RPB; r++) {
            const __half2* e = E + r * (TAGS / 2) + e0;
            __half2 acc = __hmul2(e[0], v0);
            acc = __hfma2(e[1], v1, acc);
            acc = __hfma2(e[2], v2, acc);
            acc = __hfma2(e[3], v3, acc);
            float2 f = __half22float2(acc);
            float p = f.x + f.y;
            p += __shfl_xor_sync(0xffffffffu, p, 16);
            p += __shfl_xor_sync(0xffffffffu, p, 8);
            p += __shfl_xor_sync(0xffffffffu, p, 4);
            p += __shfl_xor_sync(0xffffffffu, p, 2);
            p += __shfl_xor_sync(0xffffffffu, p, 1);
            if (lane == 0) partial[r * NWARP + warp] = p;
        }
        __syncthreads();

        // Combine warp partials, apply exp(emit), publish w and block max.
        if (tid < nrows) {
            float sum = 0.f;
#pragma unroll
            for (int w = 0; w < NWARP; w++) sum += partial[tid * NWARP + w];
            float wv = __expf(h[(size_t)t * TAGS + row0 + tid]) * sum;
            __stcg(&rout[row0 + tid], wv);
            atomicMax(&s_max, __float_as_int(wv));   // wv >= 0: int compare is order-preserving
        }
        __syncthreads();

        // Grid barrier (monotonic epochs; init kernel resets counters each launch).
        if (tid == 0) {
            if (nrows > 0) {
                atomicMax((int*)(g_Mbuf + t + 1), s_max);
                s_max = 0;
            }
            __threadfence();
            unsigned n = atomicAdd(&g_arrive, 1u);
            if (n == (unsigned)(t + 1) * NB - 1u) {
                g_release = (unsigned)(t + 1);
                __threadfence();
            } else {
                while (g_release < (unsigned)(t + 1)) { }
                __threadfence();
            }
        }
        __syncthreads();
    }

    // Epilogue: result = sum_t log(m_t) - S*log(alpha) + log( sum_j r_S[j] * exp(tr[END,j]) )
    if (b == 0) {
        float* redf = (float*)(smem + E_H2);             // 256 floats
        double* redd = (double*)(redf + TPB);            // 256 doubles (8B aligned)
        float dpart = 0.f;
        for (int j = tid; j < TAGS; j += TPB)
            dpart += __ldcg(&g_wbuf[0][j]) * __expf(tr[(size_t)END_IDX * TAGS + j]);
        double lpart = 0.0;
        for (int t = tid; t < S_LEN; t += TPB)
            lpart += (double)logf(__ldcg(&g_Mbuf[t]));
        redf[tid] = dpart;
        redd[tid] = lpart;
        __syncthreads();
        for (int off = TPB / 2; off > 0; off >>= 1) {
            if (tid < off) { redf[tid] += redf[tid + off]; redd[tid] += redd[tid + off]; }
            __syncthreads();
        }
        if (tid == 0)
            out[0] = (float)(redd[0] + log((double)redf[0]) -
                             (double)S_LEN * log((double)ALPHA));
    }
}

extern "C" void kernel_launch(void* const* d_in, const int* in_sizes, int n_in,
                              void* d_out, int out_size) {
    const float* a = (const float*)d_in[0];
    const float* bb = (const float*)d_in[1];
    const float* h;
    const float* tr;
    if (in_sizes[0] == S_LEN * TAGS) { h = a; tr = bb; }
    else { h = bb; tr = a; }

    cudaFuncSetAttribute(crf_main, cudaFuncAttributeMaxDynamicSharedMemorySize, SMEM_BYTES);
    crf_init<<<64, 256>>>();
    crf_main<<<NB, TPB, SMEM_BYTES>>>(h, tr, (float*)d_out);
}

// round 2
// speedup vs baseline: 1.5712x; 1.5712x over previous
#include <cuda_runtime.h>
#include <cuda_fp16.h>
#include <math.h>

#define S_LEN 8192
#define TAGS 2048
#define RPB 14
#define NB 147                 // 146*14 + 4 = 2048 rows
#define TPB 512
#define NWARP 16
#define JW (TAGS / NWARP)      // 128 j-columns per warp
#define JL (JW / 2)            // 64 j per lane (2 lanes per row per warp)
#define EH2 (JL / 2)           // 32 half2 E registers per lane
#define ALPHA 8.0f
#define START_IDX 0
#define END_IDX 1

// Persistent device state (no allocations allowed).
__device__ float g_Mbuf[S_LEN + 2];   // Mbuf[t] = max of r_t (Mbuf[0] = 1); red.max targets (>=0 bit-compatible)
__device__ float g_wbuf[2][TAGS];     // double-buffered carried vector
__device__ unsigned g_arrive;         // monotonic arrive counter

__global__ void crf_init() {
    int i = blockIdx.x * blockDim.x + threadIdx.x;
    int n = gridDim.x * blockDim.x;
    for (int t = i; t < S_LEN + 2; t += n) g_Mbuf[t] = (t == 0) ? 1.0f : 0.0f;
    for (int j = i; j < TAGS; j += n) {
        g_wbuf[0][j] = (j == START_IDX) ? 1.0f : 0.0f;
        g_wbuf[1][j] = 0.0f;
    }
    if (i == 0) g_arrive = 0u;
}

__device__ __forceinline__ __half2 f_as_h2(const float& f) {
    return *reinterpret_cast<const __half2*>(&f);
}

__global__ void __launch_bounds__(TPB, 1) crf_main(const float* __restrict__ h,
                                                   const float* __restrict__ tr,
                                                   float* __restrict__ out) {
    __shared__ __half2 vbuf[TAGS / 2];          // 4KB: current v as half2
    __shared__ float partial[NWARP][2 * RPB];   // per-warp per-(row,jhalf) partials
    __shared__ double redd[TPB];                // epilogue scratch

    const int tid = threadIdx.x;
    const int warp = tid >> 5, lane = tid & 31;
    const int b = blockIdx.x;
    const int row0 = b * RPB;
    int nrows = TAGS - row0; if (nrows > RPB) nrows = RPB;

    const bool act = lane < 2 * RPB;
    const int row = (lane < RPB) ? lane : lane - RPB;
    const int jh = (lane >= RPB) ? 1 : 0;

    // ---- One-time: this lane's E chunk = exp(transitions) -> 32 half2 registers ----
    __half2 E2[EH2];
    if (act && row < nrows) {
        const float* trow = tr + (size_t)(row0 + row) * TAGS + warp * JW + jh * JL;
#pragma unroll
        for (int q = 0; q < EH2; q++)
            E2[q] = __floats2half2_rn(__expf(trow[2 * q]), __expf(trow[2 * q + 1]));
    } else {
#pragma unroll
        for (int q = 0; q < EH2; q++) E2[q] = __floats2half2_rn(0.f, 0.f);
    }

    const float4* v4base = reinterpret_cast<const float4*>(vbuf) + (warp * 16 + jh * 8);

    for (int t = 0; t < S_LEN; t++) {
        // ---- wait for step-t inputs (single monotonic counter) ----
        if (t > 0) {
            if (tid == 0) {
                unsigned target = (unsigned)t * NB, c;
                do {
                    asm volatile("ld.relaxed.gpu.global.u32 %0, [%1];"
                                 : "=r"(c) : "l"(&g_arrive));
                } while (c < target);
                asm volatile("fence.acq_rel.gpu;" ::: "memory");
            }
            __syncthreads();
        }

        // ---- prefetch emissions for this step (overlaps everything below) ----
        float hv = 0.f;
        if (warp == 0 && lane < nrows)
            hv = __ldcg(h + (size_t)t * TAGS + row0 + lane);

        // ---- v prep: scale + fp16 convert into smem ----
        {
            float m = __ldcg(&g_Mbuf[t]);
            float s = ALPHA / m;
            float4 x = __ldcg(reinterpret_cast<const float4*>(g_wbuf[t & 1]) + tid);
            vbuf[2 * tid]     = __floats2half2_rn(x.x * s, x.y * s);
            vbuf[2 * tid + 1] = __floats2half2_rn(x.z * s, x.w * s);
        }
        __syncthreads();

        // ---- 64-j dot-product fragment per lane: 4 chains of 8 half2 (16 terms) ----
        float f0 = 0.f, f1 = 0.f;
#pragma unroll
        for (int c = 0; c < 4; c++) {
            float4 va = v4base[2 * c];
            float4 vb = v4base[2 * c + 1];
            __half2 acc = __hmul2(E2[8 * c + 0], f_as_h2(va.x));
            acc = __hfma2(E2[8 * c + 1], f_as_h2(va.y), acc);
            acc = __hfma2(E2[8 * c + 2], f_as_h2(va.z), acc);
            acc = __hfma2(E2[8 * c + 3], f_as_h2(va.w), acc);
            acc = __hfma2(E2[8 * c + 4], f_as_h2(vb.x), acc);
            acc = __hfma2(E2[8 * c + 5], f_as_h2(vb.y), acc);
            acc = __hfma2(E2[8 * c + 6], f_as_h2(vb.z), acc);
            acc = __hfma2(E2[8 * c + 7], f_as_h2(vb.w), acc);
            float2 ff = __half22float2(acc);
            f0 += ff.x; f1 += ff.y;
        }
        if (act) partial[warp][lane] = f0 + f1;
        __syncthreads();

        // ---- combine (warp 0 only), publish w, block max, arrive ----
        if (warp == 0) {
            float wv = 0.f;
            if (lane < nrows) {
                float s0 = 0.f;
#pragma unroll
                for (int w = 0; w < NWARP; w++)
                    s0 += partial[w][lane] + partial[w][lane + RPB];
                wv = __expf(hv) * s0;
                __stcg(&g_wbuf[(t + 1) & 1][row0 + lane], wv);
            }
            unsigned u = __float_as_uint(wv);   // wv >= 0: uint order == float order
#pragma unroll
            for (int o = 8; o >= 1; o >>= 1) {
                unsigned o2 = __shfl_xor_sync(0xffffffffu, u, o, 16);
                u = (o2 > u) ? o2 : u;
            }
            __syncwarp();
            if (lane == 0) {
                asm volatile("red.relaxed.gpu.global.max.u32 [%0], %1;"
                             :: "l"(reinterpret_cast<unsigned*>(&g_Mbuf[t + 1])), "r"(u) : "memory");
                asm volatile("fence.acq_rel.gpu;" ::: "memory");
                asm volatile("red.relaxed.gpu.global.add.u32 [%0], %1;"
                             :: "l"(&g_arrive), "r"(1u) : "memory");
            }
        }
        // (no bottom sync needed: top-of-loop __syncthreads gates reuse of vbuf/partial)
    }

    // ---- epilogue: block 0 only ----
    if (b == 0) {
        if (tid == 0) {
            unsigned target = (unsigned)NB * (unsigned)S_LEN, c;
            do {
                asm volatile("ld.relaxed.gpu.global.u32 %0, [%1];" : "=r"(c) : "l"(&g_arrive));
            } while (c < target);
            asm volatile("fence.acq_rel.gpu;" ::: "memory");
        }
        __syncthreads();

        float* redf = reinterpret_cast<float*>(vbuf);   // 512 floats <= 4KB
        const float* rS = g_wbuf[S_LEN & 1];
        float dpart = 0.f;
        for (int j = tid; j < TAGS; j += TPB)
            dpart += __ldcg(&rS[j]) * __expf(tr[(size_t)END_IDX * TAGS + j]);
        double lpart = 0.0;
        for (int t = tid; t < S_LEN; t += TPB)
            lpart += log((double)__ldcg(&g_Mbuf[t]));
        redf[tid] = dpart;
        redd[tid] = lpart;
        __syncthreads();
        for (int off = TPB / 2; off > 0; off >>= 1) {
            if (tid < off) { redf[tid] += redf[tid + off]; redd[tid] += redd[tid + off]; }
            __syncthreads();
        }
        if (tid == 0)
            out[0] = (float)(redd[0] + log((double)redf[0]) -
                             (double)S_LEN * log((double)ALPHA));
    }
}

extern "C" void kernel_launch(void* const* d_in, const int* in_sizes, int n_in,
                              void* d_out, int out_size) {
    const float* a = (const float*)d_in[0];
    const float* bb = (const float*)d_in[1];
    const float* h;
    const float* tr;
    if (in_sizes[0] == S_LEN * TAGS) { h = a; tr = bb; }
    else { h = bb; tr = a; }

    crf_init<<<64, 256>>>();
    crf_main<<<NB, TPB>>>(h, tr, (float*)d_out);
}